// round 11
// baseline (speedup 1.0000x reference)
#include <cuda_runtime.h>
#include <cuda_fp16.h>

#define NPTS  (1u << 18)
#define TMASK 0x3FFFFFu
#define PI2C  2654435761u
#define PTS_PER_BLK 16
#define FSCALE 16384.0f              // 2^14: lift features into fp16 normal range
#define INV_FSCALE 6.103515625e-05f  // 2^-14, exact power of two

// NL[l] = floor(16 * 1.26^l) per reference fp32 math
__device__ __constant__ float c_NL[16] = {
    16.f, 20.f, 25.f, 32.f, 40.f, 50.f, 64.f, 80.f,
    101.f, 128.f, 161.f, 203.f, 256.f, 322.f, 406.f, 512.f
};
// Dense grid width per level: W = NL + 3
__device__ __constant__ int c_W[16] = {
    19, 23, 28, 35, 43, 53, 67, 83, 104, 131, 164, 206, 259, 325, 409, 515
};
// Tile-grid dims: tiles are 8 (x) x 4 (y) half2 cells = 128B = 1 line
__device__ __constant__ int c_Wt8[16] = {
    3, 3, 4, 5, 6, 7, 9, 11, 13, 17, 21, 26, 33, 41, 52, 65
};
__device__ __constant__ int c_Ht4[16] = {
    5, 6, 7, 9, 11, 14, 17, 21, 26, 33, 41, 52, 65, 82, 103, 129
};
// Prefix sums of Wt8*Ht4*32 cells
__device__ __constant__ int c_tbase[16] = {
    0, 480, 1056, 1952, 3392, 5504, 8640, 13536,
    20928, 31744, 49696, 77248, 120512, 189152, 296736, 468128
};
#define DENSE_TOTAL 736448
#define MAX_LVL_CELLS 268320

// Dense per-level grids, fp16 feature pairs, 8x4-cell line-aligned tiles (2.9 MB)
__device__ __align__(128) __half2 g_dense[DENSE_TOTAL];

// ---------------------------------------------------------------------------
// Pre-pass: hash once per reachable grid cell; scale by 2^14 and store half2
// in the tiled layout.
// ---------------------------------------------------------------------------
__global__ void __launch_bounds__(256)
densify_kernel(const float* __restrict__ tab) {
    int l = blockIdx.y;
    int W = c_W[l];
    int Wt8 = c_Wt8[l];
    int tot = Wt8 * c_Ht4[l] * 32;
    int idx = blockIdx.x * 256 + threadIdx.x;
    if (idx >= tot) return;
    int t = idx >> 5;                 // tile id
    int off = idx & 31;               // cell within tile
    int ty = t / Wt8;
    int tx = t - ty * Wt8;
    int cx = tx * 8 + (off & 7);
    int cy = ty * 4 + (off >> 3);
    if (cx >= W || cy >= W) return;   // padding cells never read
    unsigned h = (((unsigned)cx) ^ ((unsigned)cy * PI2C)) & TMASK;
    const float* r = tab + h * 32u;
    g_dense[c_tbase[l] + idx] =
        __floats2half2_rn(__ldg(r + l) * FSCALE, __ldg(r + l + 16) * FSCALE);
}

// Catmull-Rom weight polynomial coefficients for tap k: w_k(t)=At^3+Bt^2+Ct+D
// (derived from the reference Hermite + finite-difference construction)
__device__ __forceinline__ void cub_coef(int k, float& A, float& B, float& C, float& D) {
    if (k == 0)      { A = -0.5f; B =  1.0f; C = -0.5f; D = 0.f; }
    else if (k == 1) { A =  1.5f; B = -2.5f; C =  0.0f; D = 1.f; }
    else if (k == 2) { A = -1.5f; B =  2.0f; C =  0.5f; D = 0.f; }
    else             { A =  0.5f; B = -0.5f; C =  0.0f; D = 0.f; }
}

// ---------------------------------------------------------------------------
// Main kernel: 256 threads = 16 levels x 16 taps, looping over 16 points.
// One half2 gather per lane (~2.4 lines per 16-lane window), 5-shuffle
// feature-split reduction in fp32.
// ---------------------------------------------------------------------------
__global__ void __launch_bounds__(256)
enc_cubic_kernel(const float* __restrict__ x,
                 float* __restrict__ out) {
    int tid = threadIdx.x;
    int l = tid >> 4;          // level
    int lane16 = tid & 15;     // tap id within group
    int i = lane16 & 3;        // x tap offset
    int j = lane16 >> 2;       // y tap offset

    // Lane-constant state
    float NL = c_NL[l];
    int Wt8 = c_Wt8[l];
    const __half2* grid = g_dense + c_tbase[l];
    float Ax, Bx, Cx, Dx, Ay, By, Cy, Dy;
    cub_coef(i, Ax, Bx, Cx, Dx);
    cub_coef(j, Ay, By, Cy, Dy);
    // Fold the exact 2^-14 descale into the y-polynomial (lane constants)
    Ay *= INV_FSCALE; By *= INV_FSCALE; Cy *= INV_FSCALE; Dy *= INV_FSCALE;

    unsigned n0 = blockIdx.x * PTS_PER_BLK;
    const float2* xp = reinterpret_cast<const float2*>(x);
    // lane 0 of each group stores feature 0, lane 8 stores feature 1
    int ocol = l * 2 + (lane16 >> 3);
    bool storer = (lane16 & 7) == 0;

#pragma unroll
    for (int it = 0; it < PTS_PER_BLK; ++it) {
        unsigned n = n0 + it;
        float2 p = __ldg(&xp[n]);          // uniform across block
        float xs = p.x * NL;
        float ys = p.y * NL;
        int ixi = (int)xs;
        int iyi = (int)ys;
        float lx = xs - (float)ixi;
        float ly = ys - (float)iyi;

        // Tiled address (8x4-cell tiles)
        int gx = ixi + i;
        int gy = iyi + j;
        int tx = gx >> 3, ox = gx & 7;
        int ty = gy >> 2, oy = gy & 3;
        __half2 h = grid[((ty * Wt8 + tx) << 5) + (oy << 3) + ox];
        float2 f = __half22float2(h);

        float wx = fmaf(fmaf(fmaf(Ax, lx, Bx), lx, Cx), lx, Dx);
        float wy = fmaf(fmaf(fmaf(Ay, ly, By), ly, Cy), ly, Dy);
        float w = wx * wy;
        float v0 = w * f.x;
        float v1 = w * f.y;

        // Feature-split reduction: 5 shuffles.
        float pv0 = __shfl_xor_sync(0xffffffffu, v0, 8);
        float pv1 = __shfl_xor_sync(0xffffffffu, v1, 8);
        float s = (lane16 & 8) ? (v1 + pv1) : (v0 + pv0);
        s += __shfl_xor_sync(0xffffffffu, s, 4);
        s += __shfl_xor_sync(0xffffffffu, s, 2);
        s += __shfl_xor_sync(0xffffffffu, s, 1);

        if (storer)
            out[n * 32u + ocol] = s;
    }
}

extern "C" void kernel_launch(void* const* d_in, const int* in_sizes, int n_in,
                              void* d_out, int out_size) {
    const float* x   = (const float*)d_in[0];   // (262144, 2) float32
    const float* tab = (const float*)d_in[1];   // (2^22, 2, 16) float32
    float* out = (float*)d_out;                 // (262144, 32) float32

    dim3 dgrid((MAX_LVL_CELLS + 255) / 256, 16);
    densify_kernel<<<dgrid, 256>>>(tab);

    enc_cubic_kernel<<<NPTS / PTS_PER_BLK, 256>>>(x, out);
}

// round 12
// speedup vs baseline: 1.5037x; 1.5037x over previous
#include <cuda_runtime.h>
#include <cuda_fp16.h>

#define NPTS  (1u << 18)
#define TMASK 0x3FFFFFu
#define PI2C  2654435761u
#define FSCALE 16384.0f              // 2^14: lift features into fp16 normal range
#define INV_FSCALE 6.103515625e-05f  // 2^-14, exact power of two

// NL[l] = floor(16 * 1.26^l) per reference fp32 math
__device__ __constant__ float c_NL[16] = {
    16.f, 20.f, 25.f, 32.f, 40.f, 50.f, 64.f, 80.f,
    101.f, 128.f, 161.f, 203.f, 256.f, 322.f, 406.f, 512.f
};
__device__ __constant__ int c_NLi[16] = {
    16, 20, 25, 32, 40, 50, 64, 80, 101, 128, 161, 203, 256, 322, 406, 512
};
// Cell-grid width per level: W = NL + 3
__device__ __constant__ int c_W[16] = {
    19, 23, 28, 35, 43, 53, 67, 83, 104, 131, 164, 206, 259, 325, 409, 515
};
// Prefix sums of W^2 (pass-1 dense cell grid)
__device__ __constant__ int c_base[16] = {
    0, 361, 890, 1674, 2899, 4748, 7557, 12046,
    18935, 29751, 46912, 73808, 116244, 183325, 288950, 456231
};
#define DENSE1_TOTAL 721456
// Prefix sums of NL^2 (pass-2 window-block grid; window base in [0,NL)^2)
__device__ __constant__ int c_bbase[16] = {
    0, 256, 656, 1281, 2305, 3905, 6405, 10501,
    16901, 27102, 43486, 69407, 110616, 176152, 279836, 444672
};
#define NBLK_TOTAL 706816

// Pass-1 scratch: dense per-level cell grids, fp16 feature pairs (2.9 MB)
__device__ __half2 g_dense1[DENSE1_TOTAL];

// Pass-2 scratch: one 64B-aligned block per possible 4x4 window (45.2 MB).
// c[j*4+i] = features of cell (bx+i, by+j). Row j = 16B at offset j*16.
struct __align__(64) Blk { __half2 c[16]; };
__device__ Blk g_blocks[NBLK_TOTAL];

// ---------------------------------------------------------------------------
// Pass 1: hash once per reachable cell -> dense (W x W) half2 grid per level.
// ---------------------------------------------------------------------------
__global__ void __launch_bounds__(256)
densify_kernel(const float* __restrict__ tab) {
    int l = blockIdx.y;
    int W = c_W[l];
    int tot = W * W;
    int idx = blockIdx.x * 256 + threadIdx.x;
    if (idx >= tot) return;
    int cy = idx / W;
    int cx = idx - cy * W;
    unsigned h = (((unsigned)cx) ^ ((unsigned)cy * PI2C)) & TMASK;
    const float* r = tab + h * 32u;
    g_dense1[c_base[l] + idx] =
        __floats2half2_rn(__ldg(r + l) * FSCALE, __ldg(r + l + 16) * FSCALE);
}

// ---------------------------------------------------------------------------
// Pass 2: expand cell grid into per-window 64B blocks. One thread per window;
// reads are warp-coalesced rows from pass 1, writes are 4x float4.
// ---------------------------------------------------------------------------
__global__ void __launch_bounds__(256)
blockify_kernel() {
    int l = blockIdx.y;
    int NLi = c_NLi[l];
    int nblk = NLi * NLi;
    int idx = blockIdx.x * 256 + threadIdx.x;
    if (idx >= nblk) return;
    int by = idx / NLi;
    int bx = idx - by * NLi;
    int W = c_W[l];
    const __half2* src = g_dense1 + c_base[l] + by * W + bx;
    Blk* dst = g_blocks + c_bbase[l] + idx;
#pragma unroll
    for (int j = 0; j < 4; ++j) {
        float4 row;
        __half2* rc = reinterpret_cast<__half2*>(&row);
#pragma unroll
        for (int i = 0; i < 4; ++i) rc[i] = src[j * W + i];
        reinterpret_cast<float4*>(dst->c)[j] = row;
    }
}

// Row dot: r holds 4 half2 taps; returns (dot_feat0, dot_feat1) in fp32.
__device__ __forceinline__ float2 rowdot(float4 r, float w0, float w1, float w2, float w3) {
    const __half2* h = reinterpret_cast<const __half2*>(&r);
    float2 c0 = __half22float2(h[0]);
    float2 c1 = __half22float2(h[1]);
    float2 c2 = __half22float2(h[2]);
    float2 c3 = __half22float2(h[3]);
    float a = fmaf(w3, c3.x, fmaf(w2, c2.x, fmaf(w1, c1.x, w0 * c0.x)));
    float b = fmaf(w3, c3.y, fmaf(w2, c2.y, fmaf(w1, c1.y, w0 * c0.y)));
    return make_float2(a, b);
}

// ---------------------------------------------------------------------------
// Main kernel: one thread per (point, level). lane = level -> coalesced I/O.
// The whole 4x4 window arrives as 4 LDG.128 from ONE 64B-aligned block
// (single cache line). No shuffles; all reduction in-register FMA.
// ---------------------------------------------------------------------------
__global__ void __launch_bounds__(256)
enc_cubic_kernel(const float* __restrict__ x,
                 float* __restrict__ out) {
    unsigned t = blockIdx.x * 256u + threadIdx.x;
    unsigned n = t >> 4;
    int l = t & 15;

    float2 p = __ldg(&reinterpret_cast<const float2*>(x)[n]);
    float NL = c_NL[l];
    float xs = p.x * NL;
    float ys = p.y * NL;
    int ixi = (int)xs;
    int iyi = (int)ys;
    float lx = xs - (float)ixi;
    float ly = ys - (float)iyi;

    const Blk* b = g_blocks + (c_bbase[l] + iyi * c_NLi[l] + ixi);
    const float4* rows = reinterpret_cast<const float4*>(b->c);
    float4 r0 = __ldg(rows + 0);
    float4 r1 = __ldg(rows + 1);
    float4 r2 = __ldg(rows + 2);
    float4 r3 = __ldg(rows + 3);

    // Catmull-Rom weights (from the reference Hermite + FD algebra)
    float wx0 = lx * fmaf(lx, fmaf(lx, -0.5f, 1.0f), -0.5f);
    float wx1 = fmaf(lx * lx, fmaf(lx, 1.5f, -2.5f), 1.0f);
    float wx2 = lx * fmaf(lx, fmaf(lx, -1.5f, 2.0f), 0.5f);
    float wx3 = lx * lx * fmaf(lx, 0.5f, -0.5f);
    float wy0 = ly * fmaf(ly, fmaf(ly, -0.5f, 1.0f), -0.5f);
    float wy1 = fmaf(ly * ly, fmaf(ly, 1.5f, -2.5f), 1.0f);
    float wy2 = ly * fmaf(ly, fmaf(ly, -1.5f, 2.0f), 0.5f);
    float wy3 = ly * ly * fmaf(ly, 0.5f, -0.5f);

    float2 d0 = rowdot(r0, wx0, wx1, wx2, wx3);
    float2 d1 = rowdot(r1, wx0, wx1, wx2, wx3);
    float2 d2 = rowdot(r2, wx0, wx1, wx2, wx3);
    float2 d3 = rowdot(r3, wx0, wx1, wx2, wx3);

    float o0 = fmaf(wy3, d3.x, fmaf(wy2, d2.x, fmaf(wy1, d1.x, wy0 * d0.x)));
    float o1 = fmaf(wy3, d3.y, fmaf(wy2, d2.y, fmaf(wy1, d1.y, wy0 * d0.y)));

    reinterpret_cast<float2*>(out)[n * 16u + l] =
        make_float2(o0 * INV_FSCALE, o1 * INV_FSCALE);
}

extern "C" void kernel_launch(void* const* d_in, const int* in_sizes, int n_in,
                              void* d_out, int out_size) {
    const float* x   = (const float*)d_in[0];   // (262144, 2) float32
    const float* tab = (const float*)d_in[1];   // (2^22, 2, 16) float32
    float* out = (float*)d_out;                 // (262144, 32) float32

    // Pass 1: dense cell grids (max W^2 = 265225)
    dim3 g1((265225 + 255) / 256, 16);
    densify_kernel<<<g1, 256>>>(tab);

    // Pass 2: window blocks (max NL^2 = 262144)
    dim3 g2((262144 + 255) / 256, 16);
    blockify_kernel<<<g2, 256>>>();

    // Main: one thread per (point, level)
    enc_cubic_kernel<<<(NPTS * 16) / 256, 256>>>(x, out);
}

// round 13
// speedup vs baseline: 1.7030x; 1.1325x over previous
#include <cuda_runtime.h>
#include <cuda_fp16.h>

#define NPTS  (1u << 18)
#define TMASK 0x3FFFFFu
#define PI2C  2654435761u
#define FSCALE 16384.0f              // 2^14: lift features into fp16 normal range
#define INV_FSCALE 6.103515625e-05f  // 2^-14, exact power of two
#define PTS_PER_WARP 32

// NL[l] = floor(16 * 1.26^l) per reference fp32 math
__device__ __constant__ float c_NL[16] = {
    16.f, 20.f, 25.f, 32.f, 40.f, 50.f, 64.f, 80.f,
    101.f, 128.f, 161.f, 203.f, 256.f, 322.f, 406.f, 512.f
};
__device__ __constant__ int c_NLi[16] = {
    16, 20, 25, 32, 40, 50, 64, 80, 101, 128, 161, 203, 256, 322, 406, 512
};
// Cell-grid width per level: W = NL + 3
__device__ __constant__ int c_W[16] = {
    19, 23, 28, 35, 43, 53, 67, 83, 104, 131, 164, 206, 259, 325, 409, 515
};
// Prefix sums of W^2 (pass-1 dense cell grid)
__device__ __constant__ int c_base[16] = {
    0, 361, 890, 1674, 2899, 4748, 7557, 12046,
    18935, 29751, 46912, 73808, 116244, 183325, 288950, 456231
};
#define DENSE1_TOTAL 721456
// Prefix sums of NL^2 (pass-2 window-block grid; window base in [0,NL)^2)
__device__ __constant__ int c_bbase[16] = {
    0, 256, 656, 1281, 2305, 3905, 6405, 10501,
    16901, 27102, 43486, 69407, 110616, 176152, 279836, 444672
};
#define NBLK_TOTAL 706816

// Pass-1 scratch: dense per-level cell grids, fp16 feature pairs (2.9 MB)
__device__ __half2 g_dense1[DENSE1_TOTAL];

// Pass-2 scratch: one 64B-aligned block per possible 4x4 window (45.2 MB).
// c[j*4+i] = features of cell (bx+i, by+j). Row j = 16B at offset j*16.
struct __align__(64) Blk { __half2 c[16]; };
__device__ Blk g_blocks[NBLK_TOTAL];

// ---------------------------------------------------------------------------
// Pass 1: hash once per reachable cell -> dense (W x W) half2 grid per level.
// ---------------------------------------------------------------------------
__global__ void __launch_bounds__(256)
densify_kernel(const float* __restrict__ tab) {
    int l = blockIdx.y;
    int W = c_W[l];
    int tot = W * W;
    int idx = blockIdx.x * 256 + threadIdx.x;
    if (idx >= tot) return;
    int cy = idx / W;
    int cx = idx - cy * W;
    unsigned h = (((unsigned)cx) ^ ((unsigned)cy * PI2C)) & TMASK;
    const float* r = tab + h * 32u;
    g_dense1[c_base[l] + idx] =
        __floats2half2_rn(__ldg(r + l) * FSCALE, __ldg(r + l + 16) * FSCALE);
}

// ---------------------------------------------------------------------------
// Pass 2: expand cell grid into per-window 64B blocks.
// ---------------------------------------------------------------------------
__global__ void __launch_bounds__(256)
blockify_kernel() {
    int l = blockIdx.y;
    int NLi = c_NLi[l];
    int nblk = NLi * NLi;
    int idx = blockIdx.x * 256 + threadIdx.x;
    if (idx >= nblk) return;
    int by = idx / NLi;
    int bx = idx - by * NLi;
    int W = c_W[l];
    const __half2* src = g_dense1 + c_base[l] + by * W + bx;
    Blk* dst = g_blocks + c_bbase[l] + idx;
#pragma unroll
    for (int j = 0; j < 4; ++j) {
        float4 row;
        __half2* rc = reinterpret_cast<__half2*>(&row);
#pragma unroll
        for (int i = 0; i < 4; ++i) rc[i] = src[j * W + i];
        reinterpret_cast<float4*>(dst->c)[j] = row;
    }
}

// Catmull-Rom weight polynomial coefficients for tap k: w_k(t)=At^3+Bt^2+Ct+D
__device__ __forceinline__ void cub_coef(int k, float& A, float& B, float& C, float& D) {
    if (k == 0)      { A = -0.5f; B =  1.0f; C = -0.5f; D = 0.f; }
    else if (k == 1) { A =  1.5f; B = -2.5f; C =  0.0f; D = 1.f; }
    else if (k == 2) { A = -1.5f; B =  2.0f; C =  0.5f; D = 0.f; }
    else             { A =  0.5f; B = -0.5f; C =  0.0f; D = 0.f; }
}

// ---------------------------------------------------------------------------
// Main kernel: 4 lanes per (point, level) window. Each warp covers 8 levels
// (role 0: levels 0-7, role 1: levels 8-15) and loops over PTS_PER_WARP
// points. Each lane loads ONE 16B row of its window (one LDG.128 per warp
// touches only 8 distinct 64B blocks), does the x-direction dot in fp32,
// then a 4-shuffle quad reduction; lane 0 of each quad stores a coalesced
// float2 (8 quads -> 64B contiguous store per warp).
// ---------------------------------------------------------------------------
__global__ void __launch_bounds__(256)
enc_cubic_kernel(const float* __restrict__ x,
                 float* __restrict__ out) {
    unsigned gw = (blockIdx.x * 256u + threadIdx.x) >> 5;   // global warp id
    int lane = threadIdx.x & 31;
    int role = gw & 1;                    // level half
    unsigned pbase = (gw >> 1) * PTS_PER_WARP;

    int l = role * 8 + (lane >> 2);       // this lane's level
    int j = lane & 3;                     // this lane's window row

    // Lane-constant state
    float NL = c_NL[l];
    int NLi = c_NLi[l];
    const char* bp = reinterpret_cast<const char*>(g_blocks)
                   + (size_t)c_bbase[l] * 64u + (size_t)(j * 16);
    float Ay, By, Cy, Dy;
    cub_coef(j, Ay, By, Cy, Dy);
    // Fold the exact 2^-14 descale into this lane's y-coefficients
    Ay *= INV_FSCALE; By *= INV_FSCALE; Cy *= INV_FSCALE; Dy *= INV_FSCALE;

    const float2* xp = reinterpret_cast<const float2*>(x);
    float2* outp = reinterpret_cast<float2*>(out);
    bool storer = (lane & 3) == 0;

#pragma unroll 4
    for (int it = 0; it < PTS_PER_WARP; ++it) {
        unsigned n = pbase + it;
        float2 p = __ldg(&xp[n]);         // uniform across warp
        float xs = p.x * NL;
        float ys = p.y * NL;
        int ixi = (int)xs;
        int iyi = (int)ys;
        float lx = xs - (float)ixi;
        float ly = ys - (float)iyi;

        // This lane's 16B row of the window block
        const float4* rowp = reinterpret_cast<const float4*>(
            bp + (size_t)(iyi * NLi + ixi) * 64u);
        float4 r = __ldg(rowp);

        // x-direction Catmull-Rom weights (all 4 needed per lane)
        float x2 = lx * lx;
        float wx0 = lx * fmaf(lx, fmaf(lx, -0.5f, 1.0f), -0.5f);
        float wx1 = fmaf(x2, fmaf(lx, 1.5f, -2.5f), 1.0f);
        float wx2 = lx * fmaf(lx, fmaf(lx, -1.5f, 2.0f), 0.5f);
        float wx3 = x2 * fmaf(lx, 0.5f, -0.5f);
        // This lane's y weight (with 2^-14 descale folded in)
        float wy = fmaf(fmaf(fmaf(Ay, ly, By), ly, Cy), ly, Dy);

        // Row dot in fp32
        const __half2* h = reinterpret_cast<const __half2*>(&r);
        float2 c0 = __half22float2(h[0]);
        float2 c1 = __half22float2(h[1]);
        float2 c2 = __half22float2(h[2]);
        float2 c3 = __half22float2(h[3]);
        float d0 = fmaf(wx3, c3.x, fmaf(wx2, c2.x, fmaf(wx1, c1.x, wx0 * c0.x)));
        float d1 = fmaf(wx3, c3.y, fmaf(wx2, c2.y, fmaf(wx1, c1.y, wx0 * c0.y)));
        float v0 = d0 * wy;
        float v1 = d1 * wy;

        // Quad reduction, feature-split:
        //   step 1 (xor 2): lanes {0,1} of quad accumulate feature 0,
        //                   lanes {2,3} accumulate feature 1
        float p0 = __shfl_xor_sync(0xffffffffu, v0, 2);
        float p1 = __shfl_xor_sync(0xffffffffu, v1, 2);
        float s = (lane & 2) ? (v1 + p1) : (v0 + p0);
        s += __shfl_xor_sync(0xffffffffu, s, 1);
        //   lane0 has feat0 sum, lane2 has feat1 sum; bring feat1 to lane0
        float u = __shfl_xor_sync(0xffffffffu, s, 2);

        if (storer)
            outp[n * 16u + l] = make_float2(s, u);
    }
}

extern "C" void kernel_launch(void* const* d_in, const int* in_sizes, int n_in,
                              void* d_out, int out_size) {
    const float* x   = (const float*)d_in[0];   // (262144, 2) float32
    const float* tab = (const float*)d_in[1];   // (2^22, 2, 16) float32
    float* out = (float*)d_out;                 // (262144, 32) float32

    // Pass 1: dense cell grids (max W^2 = 265225)
    dim3 g1((265225 + 255) / 256, 16);
    densify_kernel<<<g1, 256>>>(tab);

    // Pass 2: window blocks (max NL^2 = 262144)
    dim3 g2((262144 + 255) / 256, 16);
    blockify_kernel<<<g2, 256>>>();

    // Main: 2 warp-roles per point-stream, 8 windows per warp iteration
    unsigned total_warps = (NPTS / PTS_PER_WARP) * 2;       // 16384 warps
    enc_cubic_kernel<<<total_warps * 32 / 256, 256>>>(x, out);
}